// round 2
// baseline (speedup 1.0000x reference)
#include <cuda_runtime.h>

// Problem constants
#define BB   8
#define ND   12288
#define NU   49152
#define CI   64
#define CO   32
#define SP   9
#define NNZE 147456
#define KTOT (SP * CI)   // 576

// Scratch (device globals — no runtime allocation allowed)
__device__ float g_pooled[(size_t)BB * NU * CI];   // [B, N_UP, C_IN] 100.7 MB
__device__ int   g_cnt[NU];
__device__ int   g_off[NU + 1];
__device__ int   g_wp[NU];
__device__ int   g_eid[NNZE];

// ---------------------------------------------------------------------------
// CSR build: zero counts -> histogram -> scan -> fill
// ---------------------------------------------------------------------------
__global__ void zero_cnt() {
    int i = blockIdx.x * blockDim.x + threadIdx.x;
    if (i < NU) g_cnt[i] = 0;
}

__global__ void hist_rows(const int* __restrict__ rows) {
    int e = blockIdx.x * blockDim.x + threadIdx.x;
    if (e < NNZE) atomicAdd(&g_cnt[__ldg(rows + e)], 1);
}

// Single-block exclusive scan over NU=49152 counts (1024 threads x 48 each).
__global__ void scan_counts() {
    __shared__ int warp_sums[32];
    const int t    = threadIdx.x;          // 0..1023
    const int lane = t & 31, w = t >> 5;
    const int base = t * (NU / 1024);      // 48 per thread

    int local = 0;
#pragma unroll 4
    for (int j = 0; j < NU / 1024; j++) local += g_cnt[base + j];

    // warp inclusive scan
    int v = local;
#pragma unroll
    for (int d = 1; d < 32; d <<= 1) {
        int n = __shfl_up_sync(0xffffffffu, v, d);
        if (lane >= d) v += n;
    }
    if (lane == 31) warp_sums[w] = v;
    __syncthreads();
    if (w == 0) {
        int s = warp_sums[lane];
#pragma unroll
        for (int d = 1; d < 32; d <<= 1) {
            int n = __shfl_up_sync(0xffffffffu, s, d);
            if (lane >= d) s += n;
        }
        warp_sums[lane] = s;   // inclusive warp totals
    }
    __syncthreads();

    int run = (v - local) + (w > 0 ? warp_sums[w - 1] : 0);   // exclusive base
#pragma unroll 4
    for (int j = 0; j < NU / 1024; j++) {
        int c = g_cnt[base + j];
        g_off[base + j] = run;
        g_wp[base + j]  = run;
        run += c;
    }
    if (t == 1023) g_off[NU] = run;
}

__global__ void fill_eid(const int* __restrict__ rows) {
    int e = blockIdx.x * blockDim.x + threadIdx.x;
    if (e < NNZE) {
        int p = atomicAdd(&g_wp[__ldg(rows + e)], 1);
        g_eid[p] = e;
    }
}

// ---------------------------------------------------------------------------
// Gather-pool: thread = (row, c4 chunk). Accumulates all 8 batches in regs,
// reads x float4 (coalesced 256B per row-group), plain float4 stores.
// ---------------------------------------------------------------------------
__global__ void __launch_bounds__(256)
gather_pool(const float* __restrict__ x,
            const int*   __restrict__ cols,
            const float* __restrict__ vals) {
    int gt  = blockIdx.x * blockDim.x + threadIdx.x;
    int row = gt >> 4;
    int c4  = gt & 15;
    if (row >= NU) return;

    int s = g_off[row];
    int e = g_off[row + 1];

    float4 acc[BB];
#pragma unroll
    for (int b = 0; b < BB; b++) acc[b] = make_float4(0.f, 0.f, 0.f, 0.f);

    for (int i = s; i < e; i++) {
        int   eid = g_eid[i];
        int   col = __ldg(cols + eid);
        float v   = __ldg(vals + eid);
        const float4* xp = reinterpret_cast<const float4*>(x) + (size_t)col * 16 + c4;
#pragma unroll
        for (int b = 0; b < BB; b++) {
            float4 xv = __ldg(xp + (size_t)b * (ND * 16));
            acc[b].x += v * xv.x;
            acc[b].y += v * xv.y;
            acc[b].z += v * xv.z;
            acc[b].w += v * xv.w;
        }
    }

    float4* pp = reinterpret_cast<float4*>(g_pooled) + (size_t)row * 16 + c4;
#pragma unroll
    for (int b = 0; b < BB; b++)
        pp[(size_t)b * (NU * 16)] = acc[b];
}

// ---------------------------------------------------------------------------
// Fused spiral gather + GEMM + bias + relu.
// Block tile 128 rows x 32 outs; thread tile 4x4; kc-step 4 with float4 LDS
// for both G and W; packed fma.rn.f32x2 accumulation.
// ---------------------------------------------------------------------------
#define TILE_R 128
#define GPAD   68   // 16B-aligned rows, bank offset 4 per row

__device__ __forceinline__ float2 ffma2(float a, float2 w, float2 c) {
    float2 r;
    asm("{\n\t"
        ".reg .b64 ra, rb, rc, rd;\n\t"
        "mov.b64 ra, {%2, %2};\n\t"
        "mov.b64 rb, {%3, %4};\n\t"
        "mov.b64 rc, {%5, %6};\n\t"
        "fma.rn.f32x2 rd, ra, rb, rc;\n\t"
        "mov.b64 {%0, %1}, rd;\n\t"
        "}"
        : "=f"(r.x), "=f"(r.y)
        : "f"(a), "f"(w.x), "f"(w.y), "f"(c.x), "f"(c.y));
    return r;
}

__global__ void __launch_bounds__(256, 2)
spiral_fused(const int*   __restrict__ sidx,
             const float* __restrict__ weight,
             const float* __restrict__ bias,
             float*       __restrict__ out) {
    extern __shared__ float sm[];
    float* Wt = sm;                  // [KTOT][CO] transposed weight, 73.7 KB
    float* G  = sm + KTOT * CO;      // [TILE_R][GPAD] gathered tile, 34.8 KB

    const int tid = threadIdx.x;
    const int b   = blockIdx.y;
    const int n0  = blockIdx.x * TILE_R;

    // Wt[k][o] = weight[o][k]
    for (int i = tid; i < KTOT * CO; i += 256) {
        int k = i >> 5;
        int o = i & 31;
        Wt[i] = __ldg(weight + o * KTOT + k);
    }

    const int to = tid & 7;     // out group: o0 = to*4
    const int tr = tid >> 3;    // row group: rows tr*4 .. tr*4+3
    const int o0 = to * 4;

    float2 acc[4][2];
#pragma unroll
    for (int i = 0; i < 4; i++) {
        acc[i][0] = make_float2(0.f, 0.f);
        acc[i][1] = make_float2(0.f, 0.f);
    }

    const float* pooledB = g_pooled + (size_t)b * NU * CI;

#pragma unroll 1
    for (int s = 0; s < SP; s++) {
        __syncthreads();   // protect G from previous iteration readers (also fences Wt at s=0)
        // Gather 128 rows x 64 ch = 2048 float4, 8 per thread.
#pragma unroll
        for (int it = 0; it < (TILE_R * 16) / 256; it++) {
            int i  = it * 256 + tid;
            int rl = i >> 4;
            int cv = (i & 15) << 2;
            int idx = __ldg(sidx + (n0 + rl) * SP + s);
            float4 v = *reinterpret_cast<const float4*>(pooledB + (size_t)idx * CI + cv);
            *reinterpret_cast<float4*>(G + rl * GPAD + cv) = v;
        }
        __syncthreads();

        const float* wk = Wt + s * CI * CO + o0;
        const float* gk = G + tr * 4 * GPAD;
#pragma unroll 4
        for (int kc = 0; kc < CI; kc += 4) {
            float4 w0 = *reinterpret_cast<const float4*>(wk + (kc + 0) * CO);
            float4 w1 = *reinterpret_cast<const float4*>(wk + (kc + 1) * CO);
            float4 w2 = *reinterpret_cast<const float4*>(wk + (kc + 2) * CO);
            float4 w3 = *reinterpret_cast<const float4*>(wk + (kc + 3) * CO);
#pragma unroll
            for (int i = 0; i < 4; i++) {
                float4 g = *reinterpret_cast<const float4*>(gk + i * GPAD + kc);
                acc[i][0] = ffma2(g.x, make_float2(w0.x, w0.y), acc[i][0]);
                acc[i][1] = ffma2(g.x, make_float2(w0.z, w0.w), acc[i][1]);
                acc[i][0] = ffma2(g.y, make_float2(w1.x, w1.y), acc[i][0]);
                acc[i][1] = ffma2(g.y, make_float2(w1.z, w1.w), acc[i][1]);
                acc[i][0] = ffma2(g.z, make_float2(w2.x, w2.y), acc[i][0]);
                acc[i][1] = ffma2(g.z, make_float2(w2.z, w2.w), acc[i][1]);
                acc[i][0] = ffma2(g.w, make_float2(w3.x, w3.y), acc[i][0]);
                acc[i][1] = ffma2(g.w, make_float2(w3.z, w3.w), acc[i][1]);
            }
        }
    }

    // Epilogue: bias + relu, float4 stores.
    float4 bv = *reinterpret_cast<const float4*>(bias + o0);
#pragma unroll
    for (int i = 0; i < 4; i++) {
        float4 r;
        r.x = fmaxf(acc[i][0].x + bv.x, 0.f);
        r.y = fmaxf(acc[i][0].y + bv.y, 0.f);
        r.z = fmaxf(acc[i][1].x + bv.z, 0.f);
        r.w = fmaxf(acc[i][1].y + bv.w, 0.f);
        int n = n0 + tr * 4 + i;
        *reinterpret_cast<float4*>(out + ((size_t)b * NU + n) * CO + o0) = r;
    }
}

// ---------------------------------------------------------------------------
// Launch
// ---------------------------------------------------------------------------
extern "C" void kernel_launch(void* const* d_in, const int* in_sizes, int n_in,
                              void* d_out, int out_size) {
    const float* x        = (const float*)d_in[0];
    const int*   up_rows  = (const int*)  d_in[1];
    const int*   up_cols  = (const int*)  d_in[2];
    const float* up_vals  = (const float*)d_in[3];
    const int*   sidx     = (const int*)  d_in[4];
    const float* weight   = (const float*)d_in[5];
    const float* bias     = (const float*)d_in[6];
    float*       out      = (float*)d_out;

    zero_cnt<<<(NU + 255) / 256, 256>>>();
    hist_rows<<<(NNZE + 255) / 256, 256>>>(up_rows);
    scan_counts<<<1, 1024>>>();
    fill_eid<<<(NNZE + 255) / 256, 256>>>(up_rows);
    gather_pool<<<(NU * 16) / 256, 256>>>(x, up_cols, up_vals);

    int smem = (KTOT * CO + TILE_R * GPAD) * (int)sizeof(float);  // 108.5 KB
    cudaFuncSetAttribute(spiral_fused,
                         cudaFuncAttributeMaxDynamicSharedMemorySize, smem);
    dim3 grid(NU / TILE_R, BB);
    spiral_fused<<<grid, 256, smem>>>(sidx, weight, bias, out);
}

// round 3
// speedup vs baseline: 1.0113x; 1.0113x over previous
#include <cuda_runtime.h>

// Problem constants
#define BB   8
#define ND   12288
#define NU   49152
#define CI   64
#define CO   32
#define SP   9
#define NNZE 147456
#define KTOT (SP * CI)   // 576

// Scratch (device globals — no runtime allocation allowed)
__device__ float g_pooled[(size_t)BB * NU * CI];   // [B, N_UP, C_IN] 100.7 MB
__device__ int   g_cnt[NU];
__device__ int   g_off[NU + 1];
__device__ int   g_wp[NU];
__device__ int   g_eid[NNZE];
__device__ float2 g_wpack[SP * (CI / 2) * CO];     // [s][kc2][o] packed weight pairs

// ---------------------------------------------------------------------------
// CSR build: zero counts -> histogram -> scan -> fill
// ---------------------------------------------------------------------------
__global__ void zero_cnt() {
    int i = blockIdx.x * blockDim.x + threadIdx.x;
    if (i < NU) g_cnt[i] = 0;
}

__global__ void hist_rows(const int* __restrict__ rows) {
    int e = blockIdx.x * blockDim.x + threadIdx.x;
    if (e < NNZE) atomicAdd(&g_cnt[__ldg(rows + e)], 1);
}

// Single-block exclusive scan over NU=49152 counts (1024 threads x 48 each).
__global__ void scan_counts() {
    __shared__ int warp_sums[32];
    const int t    = threadIdx.x;
    const int lane = t & 31, w = t >> 5;
    const int base = t * (NU / 1024);

    int local = 0;
#pragma unroll 4
    for (int j = 0; j < NU / 1024; j++) local += g_cnt[base + j];

    int v = local;
#pragma unroll
    for (int d = 1; d < 32; d <<= 1) {
        int n = __shfl_up_sync(0xffffffffu, v, d);
        if (lane >= d) v += n;
    }
    if (lane == 31) warp_sums[w] = v;
    __syncthreads();
    if (w == 0) {
        int s = warp_sums[lane];
#pragma unroll
        for (int d = 1; d < 32; d <<= 1) {
            int n = __shfl_up_sync(0xffffffffu, s, d);
            if (lane >= d) s += n;
        }
        warp_sums[lane] = s;
    }
    __syncthreads();

    int run = (v - local) + (w > 0 ? warp_sums[w - 1] : 0);
#pragma unroll 4
    for (int j = 0; j < NU / 1024; j++) {
        int c = g_cnt[base + j];
        g_off[base + j] = run;
        g_wp[base + j]  = run;
        run += c;
    }
    if (t == 1023) g_off[NU] = run;
}

__global__ void fill_eid(const int* __restrict__ rows) {
    int e = blockIdx.x * blockDim.x + threadIdx.x;
    if (e < NNZE) {
        int p = atomicAdd(&g_wp[__ldg(rows + e)], 1);
        g_eid[p] = e;
    }
}

// ---------------------------------------------------------------------------
// Weight prepack: Wp[(s*32 + kc2)*32 + o] = (W[o][s*64 + 2*kc2], W[o][s*64 + 2*kc2 + 1])
// ---------------------------------------------------------------------------
__global__ void wpack(const float* __restrict__ weight) {
    int idx = blockIdx.x * blockDim.x + threadIdx.x;
    if (idx >= SP * 32 * CO) return;
    int o   = idx & 31;
    int kc2 = (idx >> 5) & 31;
    int s   = idx >> 10;
    const float* src = weight + o * KTOT + s * CI + 2 * kc2;
    g_wpack[idx] = make_float2(src[0], src[1]);
}

// ---------------------------------------------------------------------------
// Gather-pool: thread = (row, c4 chunk). Accumulates all 8 batches in regs.
// ---------------------------------------------------------------------------
__global__ void __launch_bounds__(256)
gather_pool(const float* __restrict__ x,
            const int*   __restrict__ cols,
            const float* __restrict__ vals) {
    int gt  = blockIdx.x * blockDim.x + threadIdx.x;
    int row = gt >> 4;
    int c4  = gt & 15;
    if (row >= NU) return;

    int s = g_off[row];
    int e = g_off[row + 1];

    float4 acc[BB];
#pragma unroll
    for (int b = 0; b < BB; b++) acc[b] = make_float4(0.f, 0.f, 0.f, 0.f);

    for (int i = s; i < e; i++) {
        int   eid = g_eid[i];
        int   col = __ldg(cols + eid);
        float v   = __ldg(vals + eid);
        const float4* xp = reinterpret_cast<const float4*>(x) + (size_t)col * 16 + c4;
#pragma unroll
        for (int b = 0; b < BB; b++) {
            float4 xv = __ldg(xp + (size_t)b * (ND * 16));
            acc[b].x += v * xv.x;
            acc[b].y += v * xv.y;
            acc[b].z += v * xv.z;
            acc[b].w += v * xv.w;
        }
    }

    float4* pp = reinterpret_cast<float4*>(g_pooled) + (size_t)row * 16 + c4;
#pragma unroll
    for (int b = 0; b < BB; b++)
        pp[(size_t)b * (NU * 16)] = acc[b];
}

// ---------------------------------------------------------------------------
// Fused spiral gather + GEMM + bias + relu.
// k-paired fma.rn.f32x2: every operand is a naturally-aligned 64-bit pair
// loaded via ulonglong2 (LDS.128) — zero pack/unpack movs in the hot loop.
// acc[i][o'] holds (sum over even k, sum over odd k); horizontal add at end.
// ---------------------------------------------------------------------------
#define TILE_R 128
#define GPAD   68   // floats per G row: 272B, 16B-aligned, bank offset 4/row

__device__ __forceinline__ void ffma2(unsigned long long& acc,
                                      unsigned long long a2,
                                      unsigned long long b2) {
    asm("fma.rn.f32x2 %0, %1, %2, %0;" : "+l"(acc) : "l"(a2), "l"(b2));
}

__device__ __forceinline__ float2 unpack2(unsigned long long v) {
    float2 r;
    asm("mov.b64 {%0, %1}, %2;" : "=f"(r.x), "=f"(r.y) : "l"(v));
    return r;
}

__global__ void __launch_bounds__(256, 2)
spiral_fused(const int*   __restrict__ sidx,
             const float* __restrict__ bias,
             float*       __restrict__ out) {
    extern __shared__ float sm[];
    float* Ws = sm;                  // packed weight pairs, SP*32*32 float2 = 73.7 KB
    float* G  = sm + SP * 32 * CO * 2;   // [TILE_R][GPAD] gathered tile, 34.8 KB

    const int tid = threadIdx.x;
    const int b   = blockIdx.y;
    const int n0  = blockIdx.x * TILE_R;

    // Copy packed weights into smem (float4 = 2 packed pairs per load).
    {
        const float4* src = reinterpret_cast<const float4*>(g_wpack);
        float4*       dst = reinterpret_cast<float4*>(Ws);
#pragma unroll
        for (int i = tid; i < SP * 32 * CO / 2; i += 256)
            dst[i] = src[i];
    }

    const int to = tid & 7;     // out group: o0 = to*4
    const int tr = tid >> 3;    // row group: rows tr*4 .. tr*4+3

    unsigned long long acc[4][4];
#pragma unroll
    for (int i = 0; i < 4; i++)
#pragma unroll
        for (int j = 0; j < 4; j++) acc[i][j] = 0ull;

    const float* pooledB = g_pooled + (size_t)b * NU * CI;

#pragma unroll 1
    for (int s = 0; s < SP; s++) {
        __syncthreads();   // protect G (and Ws at s=0)
        // Gather 128 rows x 64 ch = 2048 float4, 8 per thread.
#pragma unroll
        for (int it = 0; it < (TILE_R * 16) / 256; it++) {
            int i  = it * 256 + tid;
            int rl = i >> 4;
            int cv = (i & 15) << 2;
            int idx = __ldg(sidx + (n0 + rl) * SP + s);
            float4 v = *reinterpret_cast<const float4*>(pooledB + (size_t)idx * CI + cv);
            *reinterpret_cast<float4*>(G + rl * GPAD + cv) = v;
        }
        __syncthreads();

        // ws2 indexed in ulonglong2 units: [kc2][o/2]; this thread reads o0=to*4.
        const ulonglong2* ws2 =
            reinterpret_cast<const ulonglong2*>(Ws) + (size_t)s * 32 * 16 + to * 2;
        const float* gk = G + tr * 4 * GPAD;

#pragma unroll 4
        for (int kc2 = 0; kc2 < 32; kc2 += 2) {   // 4 k-channels per iter
            ulonglong2 wA0 = ws2[(size_t)kc2 * 16];          // k-pair kc2: (o0,o0+1)
            ulonglong2 wA1 = ws2[(size_t)kc2 * 16 + 1];      //              (o0+2,o0+3)
            ulonglong2 wB0 = ws2[(size_t)(kc2 + 1) * 16];    // k-pair kc2+1
            ulonglong2 wB1 = ws2[(size_t)(kc2 + 1) * 16 + 1];
#pragma unroll
            for (int i = 0; i < 4; i++) {
                ulonglong2 g = *reinterpret_cast<const ulonglong2*>(gk + i * GPAD + 2 * kc2);
                ffma2(acc[i][0], g.x, wA0.x);
                ffma2(acc[i][1], g.x, wA0.y);
                ffma2(acc[i][2], g.x, wA1.x);
                ffma2(acc[i][3], g.x, wA1.y);
                ffma2(acc[i][0], g.y, wB0.x);
                ffma2(acc[i][1], g.y, wB0.y);
                ffma2(acc[i][2], g.y, wB1.x);
                ffma2(acc[i][3], g.y, wB1.y);
            }
        }
    }

    // Epilogue: horizontal add of k-parity halves, bias + relu, float4 store.
    const int o0 = to * 4;
    float4 bv = *reinterpret_cast<const float4*>(bias + o0);
#pragma unroll
    for (int i = 0; i < 4; i++) {
        float2 a0 = unpack2(acc[i][0]);
        float2 a1 = unpack2(acc[i][1]);
        float2 a2 = unpack2(acc[i][2]);
        float2 a3 = unpack2(acc[i][3]);
        float4 r;
        r.x = fmaxf(a0.x + a0.y + bv.x, 0.f);
        r.y = fmaxf(a1.x + a1.y + bv.y, 0.f);
        r.z = fmaxf(a2.x + a2.y + bv.z, 0.f);
        r.w = fmaxf(a3.x + a3.y + bv.w, 0.f);
        int n = n0 + tr * 4 + i;
        *reinterpret_cast<float4*>(out + ((size_t)b * NU + n) * CO + o0) = r;
    }
}

// ---------------------------------------------------------------------------
// Launch
// ---------------------------------------------------------------------------
extern "C" void kernel_launch(void* const* d_in, const int* in_sizes, int n_in,
                              void* d_out, int out_size) {
    const float* x        = (const float*)d_in[0];
    const int*   up_rows  = (const int*)  d_in[1];
    const int*   up_cols  = (const int*)  d_in[2];
    const float* up_vals  = (const float*)d_in[3];
    const int*   sidx     = (const int*)  d_in[4];
    const float* weight   = (const float*)d_in[5];
    const float* bias     = (const float*)d_in[6];
    float*       out      = (float*)d_out;

    zero_cnt<<<(NU + 255) / 256, 256>>>();
    hist_rows<<<(NNZE + 255) / 256, 256>>>(up_rows);
    scan_counts<<<1, 1024>>>();
    fill_eid<<<(NNZE + 255) / 256, 256>>>(up_rows);
    wpack<<<(SP * 32 * CO + 255) / 256, 256>>>(weight);
    gather_pool<<<(NU * 16) / 256, 256>>>(x, up_cols, up_vals);

    int smem = (SP * 32 * CO * 2 + TILE_R * GPAD) * (int)sizeof(float);  // 108.5 KB
    cudaFuncSetAttribute(spiral_fused,
                         cudaFuncAttributeMaxDynamicSharedMemorySize, smem);
    dim3 grid(NU / TILE_R, BB);
    spiral_fused<<<grid, 256, smem>>>(sidx, bias, out);
}